// round 10
// baseline (speedup 1.0000x reference)
#include <cuda_runtime.h>
#include <math.h>

// Problem constants
#define B_    32
#define C_    256
#define L_    8192
#define H_    16
#define ROWS  (B_ * C_)          // 8192
#define L4    (L_ / 4)           // 2048 float4 per row
#define ITER  8
#define TPB   256

// Queue layout (same as R7): mean-stream = per batch [256 means, 1 excite]
// = 8224 tasks; scale-stream = 8192 tasks. First LEAD positions are
// mean-stream only, then 1:1 interleave, then scale tail.
#define NM    (B_ * (C_ + 1))    // 8224
#define NS    ROWS               // 8192
#define NTASKS (NM + NS)         // 16416
#define LEAD  1028               // 4 batches of mean-stream first (> P_BLOCKS)
#define ALT_END (LEAD + 2 * (NM - LEAD))   // 15420
#define P_BLOCKS 888

// Scratch (allocation-free rule: __device__ globals)
__device__ float d_y[ROWS];
__device__ float d_g[ROWS];
__device__ int   g_cnt[B_];
__device__ int   g_flag[B_];

// ---------------------------------------------------------------------------
__global__ void se_init() {
    const int t = threadIdx.x;
    if (t < B_) { g_cnt[t] = 0; g_flag[t] = 0; }
}

// ---------------------------------------------------------------------------
// Persistent worker, STATIC round-robin over queue positions: block i takes
// positions i, i+888, ... No dispatch atomic, no task-id broadcast barrier.
// ---------------------------------------------------------------------------
__global__ __launch_bounds__(TPB, 6) void se_persist(const float4* __restrict__ x,
                                                     float4* __restrict__ out,
                                                     const float* __restrict__ W1,
                                                     const float* __restrict__ W2) {
    __shared__ float warp_sums[8];
    __shared__ float ys[C_];
    __shared__ float hs[H_];

    const int t    = threadIdx.x;
    const int lane = t & 31;
    const int wid  = t >> 5;

    for (int task = blockIdx.x; task < NTASKS; task += P_BLOCKS) {
        // ---- map queue position -> (stream, index); all threads compute locally
        int mean_idx = -1, scale_idx = -1;
        if (task < LEAD) {
            mean_idx = task;
        } else if (task < ALT_END) {
            const int j = task - LEAD;
            if (j & 1) mean_idx = LEAD + (j >> 1);
            else       scale_idx = j >> 1;
        } else {
            scale_idx = (NM - LEAD) + (task - ALT_END);
        }

        if (mean_idx >= 0) {
            const int b = mean_idx / (C_ + 1);
            const int r = mean_idx - b * (C_ + 1);
            if (r < C_) {
                // ---- MEAN of row (b, r): default policy -> lines persist in L2
                const int row = b * C_ + r;
                const float4* __restrict__ p = x + (size_t)row * L4;
                float s = 0.0f;
                #pragma unroll
                for (int i = 0; i < ITER; ++i) {
                    float4 v = __ldg(p + t + i * 256);
                    s += (v.x + v.y) + (v.z + v.w);
                }
                #pragma unroll
                for (int off = 16; off > 0; off >>= 1)
                    s += __shfl_xor_sync(0xFFFFFFFFu, s, off);
                if (lane == 0) warp_sums[wid] = s;
                __syncthreads();
                if (wid == 0) {
                    float tt = (lane < 8) ? warp_sums[lane] : 0.0f;
                    #pragma unroll
                    for (int off = 4; off > 0; off >>= 1)
                        tt += __shfl_xor_sync(0xFFFFFFFFu, tt, off);
                    if (lane == 0) {
                        d_y[row] = tt * (1.0f / (float)L_);
                        __threadfence();                    // release d_y
                        atomicAdd(&g_cnt[b], 1);
                    }
                }
                __syncthreads();   // warp_sums reuse safety
            } else {
                // ---- EXCITE for batch b (spins only on trailing in-flight means)
                if (t == 0) {
                    while (((volatile int*)g_cnt)[b] < C_) __nanosleep(32);
                }
                __syncthreads();
                __threadfence();                            // acquire
                ys[t] = __ldcg(&d_y[b * C_ + t]);
                __syncthreads();
                {
                    const int hh = t >> 4;
                    const int k  = t & 15;
                    const float* __restrict__ w1 = W1 + hh * C_ + k * 16;
                    const float* __restrict__ yy = ys + k * 16;
                    float s = 0.0f;
                    #pragma unroll
                    for (int i = 0; i < 16; ++i) s += yy[i] * w1[i];
                    #pragma unroll
                    for (int off = 8; off > 0; off >>= 1)
                        s += __shfl_down_sync(0xFFFFFFFFu, s, off, 16);
                    if (k == 0) hs[hh] = fmaxf(s, 0.0f);
                }
                __syncthreads();
                {
                    float s = 0.0f;
                    const float* __restrict__ w2 = W2 + t * H_;
                    #pragma unroll
                    for (int j = 0; j < H_; ++j) s += hs[j] * w2[j];
                    d_g[b * C_ + t] = 1.0f / (1.0f + expf(-s));
                }
                __threadfence();                            // release d_g
                __syncthreads();
                if (t == 0) atomicExch(&g_flag[b], 1);
                __syncthreads();   // ys/hs reuse safety
            }
        } else {
            // ---- SCALE row: its excite sits ~1300+ queue positions earlier ----
            const int row = scale_idx;
            const int b   = row >> 8;
            if (t == 0) {
                while (((volatile int*)g_flag)[b] == 0) __nanosleep(32);
            }
            __syncthreads();
            __threadfence();                                // acquire
            const float gv = __ldcg(&d_g[row]);

            const float4* __restrict__ px = x   + (size_t)row * L4 + t;
            float4* __restrict__       po = out + (size_t)row * L4 + t;
            #pragma unroll
            for (int g2 = 0; g2 < 2; ++g2) {
                float4 v[4];
                #pragma unroll
                for (int i = 0; i < 4; ++i)
                    v[i] = __ldcs(px + (g2 * 4 + i) * 256);
                #pragma unroll
                for (int i = 0; i < 4; ++i) {
                    v[i].x *= gv; v[i].y *= gv; v[i].z *= gv; v[i].w *= gv;
                    __stcs(po + (g2 * 4 + i) * 256, v[i]);
                }
            }
            // no smem used -> no trailing barrier needed
        }
    }
}

// ---------------------------------------------------------------------------
extern "C" void kernel_launch(void* const* d_in, const int* in_sizes, int n_in,
                              void* d_out, int out_size) {
    const float4* x  = (const float4*)d_in[0];
    const float*  W1 = (const float*)d_in[1];
    const float*  W2 = (const float*)d_in[2];
    float4* out = (float4*)d_out;

    se_init<<<1, 64>>>();
    se_persist<<<P_BLOCKS, TPB>>>(x, out, W1, W2);
}

// round 11
// speedup vs baseline: 1.1923x; 1.1923x over previous
#include <cuda_runtime.h>
#include <math.h>

// Problem constants
#define B_    32
#define C_    256
#define L_    8192
#define H_    16
#define ROWS  (B_ * C_)          // 8192
#define L4    (L_ / 4)           // 2048 float4 per row
#define TPB   256

// Fat tasks: 2 rows per task.
// mean-stream: per batch [128 mean-tasks, 1 excite] = 129*32 = 4128
// scale-stream: 128*32 = 4096
#define MT_PER_B 129
#define NMT   (B_ * MT_PER_B)    // 4128
#define NST   (B_ * 128)         // 4096
#define NTASKS (NMT + NST)       // 8224
#define LEAD  1032               // 8 batches of mean-stream first (> grid)
#define ALT_END (LEAD + 2 * (NMT - LEAD))   // 7224
#define P_BLOCKS 888

// Scratch (allocation-free rule: __device__ globals)
__device__ float d_y[ROWS];
__device__ float d_g[ROWS];
__device__ int   g_task;
__device__ int   g_cnt[B_];
__device__ int   g_flag[B_];

// ---------------------------------------------------------------------------
__global__ void se_init() {
    const int t = threadIdx.x;
    if (t == 0) g_task = 0;
    if (t < B_) { g_cnt[t] = 0; g_flag[t] = 0; }
}

// ---------------------------------------------------------------------------
// Persistent worker. Dynamic IN-ORDER atomic queue (grab -> finish -> grab):
// the grab order doubles as a completion frontier, so a task ~grid positions
// back is provably done — that property regulates both dependency waits and
// L2 reuse distance. Do not prefetch task ids; do not assign statically.
// ---------------------------------------------------------------------------
__global__ __launch_bounds__(TPB, 6) void se_persist(const float4* __restrict__ x,
                                                     float4* __restrict__ out,
                                                     const float* __restrict__ W1,
                                                     const float* __restrict__ W2) {
    __shared__ int   s_task;
    __shared__ float warp_sums[8];
    __shared__ float ys[C_];
    __shared__ float hs[H_];

    const int t    = threadIdx.x;
    const int lane = t & 31;
    const int wid  = t >> 5;

    for (;;) {
        if (t == 0) s_task = atomicAdd(&g_task, 1);
        __syncthreads();
        const int task = s_task;
        if (task >= NTASKS) return;

        // ---- queue position -> (stream, index) ----
        int mean_idx = -1, scale_idx = -1;
        if (task < LEAD) {
            mean_idx = task;
        } else if (task < ALT_END) {
            const int j = task - LEAD;
            if (j & 1) mean_idx = LEAD + (j >> 1);
            else       scale_idx = j >> 1;
        } else {
            scale_idx = (NMT - LEAD) + (task - ALT_END);
        }

        if (mean_idx >= 0) {
            const int b = mean_idx / MT_PER_B;
            const int r = mean_idx - b * MT_PER_B;
            if (r < 128) {
                // ---- MEAN task: rows (b, 2r) and (b, 2r+1).
                // Warp-split: warps 0-3 -> row0, warps 4-7 -> row1.
                // 128 threads per row, 16 float4 each (two batched groups of 8).
                const int half = wid >> 2;              // 0 or 1
                const int ht   = t & 127;               // tid within half
                const int row  = b * C_ + 2 * r + half;
                const float4* __restrict__ p = x + (size_t)row * L4;

                float s = 0.0f;
                #pragma unroll
                for (int g2 = 0; g2 < 2; ++g2) {
                    float4 v[8];
                    #pragma unroll
                    for (int i = 0; i < 8; ++i)
                        v[i] = __ldg(p + ht + (g2 * 8 + i) * 128);
                    #pragma unroll
                    for (int i = 0; i < 8; ++i)
                        s += (v[i].x + v[i].y) + (v[i].z + v[i].w);
                }
                #pragma unroll
                for (int off = 16; off > 0; off >>= 1)
                    s += __shfl_xor_sync(0xFFFFFFFFu, s, off);
                if (lane == 0) warp_sums[wid] = s;
                __syncthreads();
                // warp 0 reduces half0 (sums 0..3), warp 4 reduces half1 (4..7)
                if ((wid & 3) == 0) {
                    float tt = (lane < 4) ? warp_sums[(wid & 4) + lane] : 0.0f;
                    tt += __shfl_xor_sync(0xFFFFFFFFu, tt, 1);
                    tt += __shfl_xor_sync(0xFFFFFFFFu, tt, 2);
                    if (lane == 0) {
                        d_y[row] = tt * (1.0f / (float)L_);
                        __threadfence();                 // release d_y
                        atomicAdd(&g_cnt[b], 1);
                    }
                }
            } else {
                // ---- EXCITE for batch b (waits only on trailing in-flight means)
                if (t == 0) {
                    while (((volatile int*)g_cnt)[b] < C_) __nanosleep(32);
                }
                __syncthreads();
                __threadfence();                         // acquire
                ys[t] = __ldcg(&d_y[b * C_ + t]);
                __syncthreads();
                {
                    const int hh = t >> 4;
                    const int k  = t & 15;
                    const float* __restrict__ w1 = W1 + hh * C_ + k * 16;
                    const float* __restrict__ yy = ys + k * 16;
                    float s = 0.0f;
                    #pragma unroll
                    for (int i = 0; i < 16; ++i) s += yy[i] * w1[i];
                    #pragma unroll
                    for (int off = 8; off > 0; off >>= 1)
                        s += __shfl_down_sync(0xFFFFFFFFu, s, off, 16);
                    if (k == 0) hs[hh] = fmaxf(s, 0.0f);
                }
                __syncthreads();
                {
                    float s = 0.0f;
                    const float* __restrict__ w2 = W2 + t * H_;
                    #pragma unroll
                    for (int j = 0; j < H_; ++j) s += hs[j] * w2[j];
                    d_g[b * C_ + t] = 1.0f / (1.0f + expf(-s));
                }
                __threadfence();                         // release d_g
                __syncthreads();
                if (t == 0) atomicExch(&g_flag[b], 1);
            }
        } else {
            // ---- SCALE task: rows 2*scale_idx, 2*scale_idx+1 (one ramp) ----
            const int row0 = 2 * scale_idx;
            const int b    = row0 >> 8;
            if (t == 0) {
                while (((volatile int*)g_flag)[b] == 0) __nanosleep(32);
            }
            __syncthreads();
            __threadfence();                             // acquire

            #pragma unroll
            for (int rr = 0; rr < 2; ++rr) {
                const int row = row0 + rr;
                const float gv = __ldcg(&d_g[row]);
                const float4* __restrict__ px = x   + (size_t)row * L4 + t;
                float4* __restrict__       po = out + (size_t)row * L4 + t;
                #pragma unroll
                for (int g2 = 0; g2 < 2; ++g2) {
                    float4 v[4];
                    #pragma unroll
                    for (int i = 0; i < 4; ++i)
                        v[i] = __ldcs(px + (g2 * 4 + i) * 256);
                    #pragma unroll
                    for (int i = 0; i < 4; ++i) {
                        v[i].x *= gv; v[i].y *= gv; v[i].z *= gv; v[i].w *= gv;
                        __stcs(po + (g2 * 4 + i) * 256, v[i]);
                    }
                }
            }
        }
        __syncthreads();   // smem reuse safety across tasks
    }
}

// ---------------------------------------------------------------------------
extern "C" void kernel_launch(void* const* d_in, const int* in_sizes, int n_in,
                              void* d_out, int out_size) {
    const float4* x  = (const float4*)d_in[0];
    const float*  W1 = (const float*)d_in[1];
    const float*  W2 = (const float*)d_in[2];
    float4* out = (float4*)d_out;

    se_init<<<1, 64>>>();
    se_persist<<<P_BLOCKS, TPB>>>(x, out, W1, W2);
}